// round 17
// baseline (speedup 1.0000x reference)
#include <cuda_runtime.h>
#include <cstddef>

#define T_STEPS 512
#define BATCH   64
#define HID     512
#define GATES   2048
#define NLAYER  2
#define MROWS   (T_STEPS * BATCH)   // 32768
#define NB      128                 // persistent CTAs (1 per SM)
#define NGRP    4                   // independent batch groups
#define GRP_CTAS 64                 // CTAs arriving per group barrier

// ---------------- device scratch (static allocation — allowed) ----------------
__device__ float g_xw[(size_t)MROWS * GATES];            // 256 MB input projection
__device__ float g_seq1[(size_t)T_STEPS * BATCH * HID];  // 64 MB layer-0 output
__device__ float g_hT[2 * NGRP * HID * 16];              // transposed h [buf][grp][u][b]
__device__ float g_wpT[(size_t)NLAYER * HID * GATES];    // packed W_hh [l][k][gate][u]

// 2-level tree barrier: 8 sub lines + 1 super + 1 sense line per group
__device__ unsigned g_sub[NGRP * 8 * 32];
__device__ unsigned g_sup[NGRP * 32];
__device__ unsigned g_sns[NGRP * 32];

// ---------------- f32x2 helpers ------------------------------------------------
__device__ __forceinline__ unsigned long long pk2(float lo, float hi) {
    unsigned long long r;
    asm("mov.b64 %0, {%1, %2};" : "=l"(r) : "f"(lo), "f"(hi));
    return r;
}
__device__ __forceinline__ unsigned long long ffma2(
    unsigned long long a, unsigned long long b, unsigned long long c) {
    unsigned long long d;
    asm("fma.rn.f32x2 %0, %1, %2, %3;" : "=l"(d) : "l"(a), "l"(b), "l"(c));
    return d;
}
__device__ __forceinline__ void unpk2(unsigned long long v, float& lo, float& hi) {
    asm("mov.b64 {%0, %1}, %2;" : "=f"(lo), "=f"(hi) : "l"(v));
}

// ---------------- pack W_hh into [k][gate][u] ----------------------------------
__global__ void pack_whh(const float* __restrict__ W_hh)
{
    int idx = blockIdx.x * 256 + threadIdx.x;
    int l = idx / (HID * GATES);
    int r = idx - l * (HID * GATES);
    int k    = r >> 11;
    int q    = r & 2047;
    int gate = q >> 9;
    int u    = q & 511;
    g_wpT[idx] = W_hh[((size_t)l * GATES + gate * HID + u) * HID + k];
}

// ---------------- SGEMM (R12-proven, unchanged) --------------------------------
__global__ void __launch_bounds__(256, 3) gemm_bias(
    const float* __restrict__ A,
    const float* __restrict__ W,
    const float* __restrict__ bih,
    const float* __restrict__ bhh,
    float* __restrict__ C)
{
    __shared__ __align__(16) float As[2][16][128];
    __shared__ __align__(16) float Bs[2][16][64];

    int tid = threadIdx.x;
    int bx = blockIdx.x;
    int by = blockIdx.y;
    int tm = tid >> 4;
    int tn = tid & 15;

    unsigned long long acc2[8][2];
#pragma unroll
    for (int i = 0; i < 8; i++)
#pragma unroll
        for (int p = 0; p < 2; p++) acc2[i][p] = 0ull;

    const int rowA = by * 128;
    const int rowW = bx * 64;

#define LOAD_TILE(k0, s)                                                      \
    {                                                                         \
        _Pragma("unroll")                                                     \
        for (int r = 0; r < 2; r++) {                                         \
            int v  = tid + r * 256;                                           \
            int rr = v >> 2;                                                  \
            int kq = v & 3;                                                   \
            float4 av = *(const float4*)&A[(size_t)(rowA + rr) * HID + (k0) + kq * 4]; \
            As[s][kq * 4 + 0][rr] = av.x; As[s][kq * 4 + 1][rr] = av.y;       \
            As[s][kq * 4 + 2][rr] = av.z; As[s][kq * 4 + 3][rr] = av.w;       \
        }                                                                     \
        {                                                                     \
            int v  = tid;                                                     \
            int rr = v >> 2;                                                  \
            int kq = v & 3;                                                   \
            float4 wv = *(const float4*)&W[(size_t)(rowW + rr) * HID + (k0) + kq * 4]; \
            Bs[s][kq * 4 + 0][rr] = wv.x; Bs[s][kq * 4 + 1][rr] = wv.y;       \
            Bs[s][kq * 4 + 2][rr] = wv.z; Bs[s][kq * 4 + 3][rr] = wv.w;       \
        }                                                                     \
    }

    LOAD_TILE(0, 0)

    for (int it = 0; it < 32; it++) {
        __syncthreads();
        int s = it & 1;
        if (it + 1 < 32) LOAD_TILE((it + 1) * 16, s ^ 1)
#pragma unroll
        for (int kk = 0; kk < 16; kk++) {
            float a[8];
            float4 t0 = *(const float4*)&As[s][kk][tm * 8];
            float4 t1 = *(const float4*)&As[s][kk][tm * 8 + 4];
            a[0]=t0.x; a[1]=t0.y; a[2]=t0.z; a[3]=t0.w;
            a[4]=t1.x; a[5]=t1.y; a[6]=t1.z; a[7]=t1.w;
            float4 s0 = *(const float4*)&Bs[s][kk][tn * 4];
            unsigned long long bp[2];
            bp[0] = pk2(s0.x, s0.y); bp[1] = pk2(s0.z, s0.w);
#pragma unroll
            for (int i = 0; i < 8; i++) {
                unsigned long long ai = pk2(a[i], a[i]);
                acc2[i][0] = ffma2(ai, bp[0], acc2[i][0]);
                acc2[i][1] = ffma2(ai, bp[1], acc2[i][1]);
            }
        }
    }
#undef LOAD_TILE

    int n0 = rowW + tn * 4;
    float bias[4];
#pragma unroll
    for (int j = 0; j < 4; j++) bias[j] = bih[n0 + j] + bhh[n0 + j];
#pragma unroll
    for (int i = 0; i < 8; i++) {
        float v[4];
        unpk2(acc2[i][0], v[0], v[1]);
        unpk2(acc2[i][1], v[2], v[3]);
        size_t off = (size_t)(rowA + tm * 8 + i) * GATES + n0;
        float4 o0 = make_float4(v[0] + bias[0], v[1] + bias[1],
                                v[2] + bias[2], v[3] + bias[3]);
        *(float4*)&C[off] = o0;
    }
}

// ---------------- persistent recurrence: two-group interleave ------------------
// 128 CTAs (1/SM) = 64 half-utiles (8 units) x 2 group-pairs. 256 threads.
// CTA serves groups {2gp, 2gp+1} (same u-range -> one 64 KB W slice).
// Per step: phase(A) then phase(B); each group's barrier wait is separated
// from its arrive by the OTHER group's full compute -> propagation hidden.
// Compute/reduction per gate bitwise identical to R16's (proven rel_err 0).
__global__ void __launch_bounds__(256, 1) lstm_seq(
    const float* __restrict__ wpT,    // layer's packed W_hh [k][gate][u]
    const float* __restrict__ xw,     // [T][BATCH][GATES]
    float* __restrict__ hT,           // [2][NGRP][HID][16]
    float* __restrict__ ybase,        // [T][BATCH][HID]
    float* __restrict__ hs_out,
    float* __restrict__ cs_out)
{
    extern __shared__ __align__(16) float smem[];
    float* Wsh = smem;                 // [512][32]                       64 KB
    float* Ush = smem + 16384;         // union Hsh[512][20] | Psh[8][32][18] 40 KB

    const int tid  = threadIdx.x;
    const int warp = tid >> 5;          // k-chunk 0..7
    const int lane = tid & 31;          // gate-row 0..31
    const int uh   = blockIdx.x & 63;
    const int gp   = blockIdx.x >> 6;
    const int u0   = uh * 8;
    const int subi = uh >> 3;           // sub-counter 0..7
    const int uu = tid & 7;             // update role (tid < 128)
    const int bb = tid >> 3;            // batch 0..15 (tid < 128)
    const int kbase = warp * 64;

    // ---- load W_hh slice: Wsh[k*32 + g*8 + uu] ------------------------------
    for (int i = tid; i < 512 * 32; i += 256) {
        int luu = i & 7;
        int lg  = (i >> 3) & 3;
        int lk  = i >> 5;
        Wsh[i] = wpT[(size_t)lk * GATES + lg * HID + u0 + luu];
    }
    __syncthreads();

    // -------- one phase = one group's full step ------------------------------
    auto do_phase = [&](int t, float& c, unsigned& sn,
                        float& x0, float& x1, float& x2, float& x3,
                        int gidx, float* hTg, const float* xwg,
                        unsigned* sub, unsigned* sup, unsigned* sns) {
        float pre0 = x0, pre1 = x1, pre2 = x2, pre3 = x3;
        if (t > 0) {
            // ---- wait for this group's barrier (arrived one phase ago) ------
            if (tid == 0) {
                unsigned v;
                do {
                    asm volatile("ld.acquire.gpu.global.u32 %0, [%1];"
                                 : "=r"(v) : "l"(sns) : "memory");
                } while (v != sn);
            }
            __syncthreads();

            // ---- per-warp stage of OWN chunk: batch 8 LDG(cg), then STS -----
            const float4* src = (const float4*)(hTg +
                (size_t)((t - 1) & 1) * NGRP * HID * 16);
            const int base4 = kbase * 4;
            float4 hv[8];
#pragma unroll
            for (int i = 0; i < 8; i++)
                hv[i] = __ldcg(src + base4 + lane + i * 32);
#pragma unroll
            for (int i = 0; i < 8; i++) {
                int idx = base4 + lane + i * 32;
                int k  = idx >> 2;
                int ch = idx & 3;
                *(float4*)&Ush[k * 20 + ch * 4] = hv[i];
            }
            __syncwarp();

            // ---- compute: 1 row x 16 batches over 64 ascending k ------------
            unsigned long long acc2[8];
#pragma unroll
            for (int i = 0; i < 8; i++) acc2[i] = 0ull;
#pragma unroll 8
            for (int j = 0; j < 64; j++) {
                int k = kbase + j;
                const float* hr = &Ush[k * 20];
                ulonglong2 q0 = *(const ulonglong2*)(hr + 0);
                ulonglong2 q1 = *(const ulonglong2*)(hr + 4);
                ulonglong2 q2 = *(const ulonglong2*)(hr + 8);
                ulonglong2 q3 = *(const ulonglong2*)(hr + 12);
                float wv = Wsh[k * 32 + lane];
                unsigned long long w2 = pk2(wv, wv);
                acc2[0] = ffma2(w2, q0.x, acc2[0]);
                acc2[1] = ffma2(w2, q0.y, acc2[1]);
                acc2[2] = ffma2(w2, q1.x, acc2[2]);
                acc2[3] = ffma2(w2, q1.y, acc2[3]);
                acc2[4] = ffma2(w2, q2.x, acc2[4]);
                acc2[5] = ffma2(w2, q2.y, acc2[5]);
                acc2[6] = ffma2(w2, q3.x, acc2[6]);
                acc2[7] = ffma2(w2, q3.y, acc2[7]);
            }
            __syncthreads();   // Hsh reads done before Psh overlays union

            // ---- partials: Psh[chunk][row][b], pad 18 -----------------------
            {
                int base = warp * 576 + lane * 18;
#pragma unroll
                for (int i = 0; i < 8; i++)
                    *(unsigned long long*)&Ush[base + 2 * i] = acc2[i];
            }
            __syncthreads();

            // ---- tree reduction over chunks, + xw last ----------------------
            if (tid < 128) {
#pragma unroll
                for (int g = 0; g < 4; g++) {
                    const int o = (g * 8 + uu) * 18 + bb;
                    float a = Ush[0 * 576 + o] + Ush[1 * 576 + o];
                    float b = Ush[2 * 576 + o] + Ush[3 * 576 + o];
                    float d = Ush[4 * 576 + o] + Ush[5 * 576 + o];
                    float e = Ush[6 * 576 + o] + Ush[7 * 576 + o];
                    float s = (a + b) + (d + e);
                    if (g == 0) pre0 = s + x0;
                    else if (g == 1) pre1 = s + x1;
                    else if (g == 2) pre2 = s + x2;
                    else pre3 = s + x3;
                }
            }
        }

        float h = 0.f;
        if (tid < 128) {
            float i_ = pre0 >= 0.f ? 1.f : 0.f;
            float f_ = pre1 >= 0.f ? 1.f : 0.f;
            float gg = pre2 >= 0.f ? 1.f : 0.f;
            float o_ = pre3 >= 0.f ? 1.f : 0.f;

            c = c * f_ + i_ * gg;
            h = c * o_;

            __stcg(&hTg[(size_t)(t & 1) * NGRP * HID * 16 + (u0 + uu) * 16 + bb], h);
            if (t == T_STEPS - 1) {
                hs_out[gidx] = h;
                cs_out[gidx] = c;
            }
        }
        sn ^= 1u;
        __syncthreads();                 // all h(t) stores issued CTA-wide
        if (tid == 0) {
            unsigned old;
            asm volatile("atom.release.gpu.global.add.u32 %0, [%1], 1;"
                         : "=r"(old) : "l"(sub) : "memory");
            if (old == 7u) {
                unsigned so;
                asm volatile("atom.acq_rel.gpu.global.add.u32 %0, [%1], 1;"
                             : "=r"(so) : "l"(sup) : "memory");
                if (so == 7u) {
                    unsigned* sb0 = sub - subi * 32;   // this group's sub[0]
#pragma unroll
                    for (int i = 0; i < 8; i++)
                        asm volatile("st.relaxed.gpu.global.u32 [%0], 0;"
                                     :: "l"(sb0 + i * 32) : "memory");
                    asm volatile("st.relaxed.gpu.global.u32 [%0], 0;"
                                 :: "l"(sup) : "memory");
                    asm volatile("st.release.gpu.global.u32 [%0], %1;"
                                 :: "l"(sns), "r"(sn) : "memory");
                }
            }
        }

        // ---- overlap window (hidden under other group's work / release) -----
        if (tid < 128) {
            __stcg(&ybase[(size_t)t * BATCH * HID + gidx], h);
            if (t + 1 < T_STEPS) {
                const float* xr = xwg + (size_t)(t + 1) * BATCH * GATES;
                x0 = xr[0]; x1 = xr[512]; x2 = xr[1024]; x3 = xr[1536];
            }
        }
    };

    // -------- per-group state -------------------------------------------------
    const int gA = gp * 2, gB = gp * 2 + 1;
    float cA = 0.f, cB = 0.f;
    unsigned snA = 0u, snB = 0u;
    float* hTgA = hT + gA * (HID * 16);
    float* hTgB = hT + gB * (HID * 16);
    const int gidxA = (gA * 16 + bb) * HID + u0 + uu;   // used only when tid<128
    const int gidxB = (gB * 16 + bb) * HID + u0 + uu;
    const float* xwgA = xw + (size_t)(gA * 16 + bb) * GATES + u0 + uu;
    const float* xwgB = xw + (size_t)(gB * 16 + bb) * GATES + u0 + uu;
    unsigned* subA = &g_sub[(gA * 8 + subi) * 32];
    unsigned* subB = &g_sub[(gB * 8 + subi) * 32];
    unsigned* supA = &g_sup[gA * 32];
    unsigned* supB = &g_sup[gB * 32];
    unsigned* snsA = &g_sns[gA * 32];
    unsigned* snsB = &g_sns[gB * 32];

    float xA0 = 0.f, xA1 = 0.f, xA2 = 0.f, xA3 = 0.f;
    float xB0 = 0.f, xB1 = 0.f, xB2 = 0.f, xB3 = 0.f;
    if (tid < 128) {
        xA0 = xwgA[0]; xA1 = xwgA[512]; xA2 = xwgA[1024]; xA3 = xwgA[1536];
        xB0 = xwgB[0]; xB1 = xwgB[512]; xB2 = xwgB[1024]; xB3 = xwgB[1536];
    }

#pragma unroll 1
    for (int t = 0; t < T_STEPS; t++) {
        do_phase(t, cA, snA, xA0, xA1, xA2, xA3, gidxA, hTgA, xwgA,
                 subA, supA, snsA);
        do_phase(t, cB, snB, xB0, xB1, xB2, xB3, gidxB, hTgB, xwgB,
                 subB, supB, snsB);
    }
    // 512 flips per group sense word -> self-restoring; counters reset by releaser
}

// ---------------- launch --------------------------------------------------------
extern "C" void kernel_launch(void* const* d_in, const int* in_sizes, int n_in,
                              void* d_out, int out_size)
{
    (void)in_sizes; (void)n_in; (void)out_size;
    const float* x    = (const float*)d_in[0];
    const float* W_ih = (const float*)d_in[1];
    const float* W_hh = (const float*)d_in[2];
    const float* b_ih = (const float*)d_in[3];
    const float* b_hh = (const float*)d_in[4];
    float* out = (float*)d_out;

    float *xw, *seq1, *hT, *wpT;
    cudaGetSymbolAddress((void**)&xw,   g_xw);
    cudaGetSymbolAddress((void**)&seq1, g_seq1);
    cudaGetSymbolAddress((void**)&hT,   g_hT);
    cudaGetSymbolAddress((void**)&wpT,  g_wpT);

    const int SMEM_BYTES = (16384 + 10240) * 4;          // 106496
    cudaFuncSetAttribute(lstm_seq, cudaFuncAttributeMaxDynamicSharedMemorySize,
                         SMEM_BYTES);

    pack_whh<<<(NLAYER * HID * GATES) / 256, 256>>>(W_hh);

    const size_t TBH = (size_t)T_STEPS * BATCH * HID;

    for (int l = 0; l < NLAYER; l++) {
        const float* A = (l == 0) ? x : seq1;
        gemm_bias<<<dim3(GATES / 64, MROWS / 128), 256>>>(
            A, W_ih + (size_t)l * GATES * HID,
            b_ih + (size_t)l * GATES, b_hh + (size_t)l * GATES, xw);

        float* ybase = (l == 0) ? seq1 : out;
        float* hs = out + TBH + (size_t)l * BATCH * HID;
        float* cs = out + TBH + (size_t)NLAYER * BATCH * HID + (size_t)l * BATCH * HID;

        lstm_seq<<<NB, 256, SMEM_BYTES>>>(wpT + (size_t)l * HID * GATES,
                                          xw, hT, ybase, hs, cs);
    }
}